// round 1
// baseline (speedup 1.0000x reference)
#include <cuda_runtime.h>
#include <math.h>

// Problem constants
#define BB 4
#define LL 2048
#define DD 2048
#define RR 2048
#define DH 512
#define MM (BB * LL)          // 8192
#define NCHUNK 16
#define CHLEN (LL / NCHUNK)   // 128

// Scratch (device globals: allocation-free per harness rules)
__device__ float g_u[(size_t)MM * RR];       // u, then u_gated, (cumsum source)
__device__ float g_v[(size_t)MM * RR];       // v, then v_gated, then global_out
__device__ float g_h[(size_t)MM * DH];       // relu(x Wg1^T + bg1)
__device__ float g_part[(size_t)BB * NCHUNK * RR];

// ---------------------------------------------------------------------------
// Tiled fp32 GEMM: C[m,n] = sum_k A[m,k] * W[n,k]  (+bias[n], + epilogue)
// A: M x K row-major, W: N x K row-major.
// EPI 0: C = z                 (plain store)
// EPI 1: C = relu(z)
// EPI 2: g = sigmoid(z); C *= g; C2 *= g   (gate fusion; no store of g)
// EPI 3: C += z                (accumulate onto conv output)
// ---------------------------------------------------------------------------
#define BM 128
#define BN 128
#define BK 16
#define TM 8
#define TN 8

template <int EPI>
__global__ __launch_bounds__(256)
void sgemm_kernel(const float* __restrict__ A, const float* __restrict__ W,
                  const float* __restrict__ bias, float* __restrict__ C,
                  float* __restrict__ C2, int M, int N, int K) {
    __shared__ float As[BK][BM];
    __shared__ float Bs[BK][BN];

    const int tid  = threadIdx.x;
    const int row0 = blockIdx.y * BM;
    const int col0 = blockIdx.x * BN;

    const int tm = (tid / (BN / TN)) * TM;   // 0..120
    const int tn = (tid % (BN / TN)) * TN;   // 0..120

    // global load mapping: 256 threads load 128x16 tile via float4
    const int lrow = tid / (BK / 4);         // 0..63
    const int lcol = (tid % (BK / 4)) * 4;   // 0,4,8,12

    const float* Ap = A + (size_t)row0 * K;
    const float* Wp = W + (size_t)col0 * K;

    float acc[TM][TN];
#pragma unroll
    for (int i = 0; i < TM; i++)
#pragma unroll
        for (int j = 0; j < TN; j++) acc[i][j] = 0.0f;

    for (int k0 = 0; k0 < K; k0 += BK) {
#pragma unroll
        for (int h = 0; h < 2; h++) {
            int r = lrow + h * 64;
            float4 a4 = *(const float4*)(Ap + (size_t)r * K + k0 + lcol);
            As[lcol + 0][r] = a4.x;
            As[lcol + 1][r] = a4.y;
            As[lcol + 2][r] = a4.z;
            As[lcol + 3][r] = a4.w;
            float4 b4 = *(const float4*)(Wp + (size_t)r * K + k0 + lcol);
            Bs[lcol + 0][r] = b4.x;
            Bs[lcol + 1][r] = b4.y;
            Bs[lcol + 2][r] = b4.z;
            Bs[lcol + 3][r] = b4.w;
        }
        __syncthreads();

#pragma unroll
        for (int k = 0; k < BK; k++) {
            float ra[TM], rb[TN];
#pragma unroll
            for (int i = 0; i < TM; i++) ra[i] = As[k][tm + i];
#pragma unroll
            for (int j = 0; j < TN; j++) rb[j] = Bs[k][tn + j];
#pragma unroll
            for (int i = 0; i < TM; i++)
#pragma unroll
                for (int j = 0; j < TN; j++)
                    acc[i][j] = fmaf(ra[i], rb[j], acc[i][j]);
        }
        __syncthreads();
    }

    // epilogue
#pragma unroll
    for (int i = 0; i < TM; i++) {
        int row = row0 + tm + i;
#pragma unroll
        for (int j = 0; j < TN; j++) {
            int col = col0 + tn + j;
            float z = acc[i][j];
            if (EPI != 3 && bias != nullptr) z += bias[col];
            size_t idx = (size_t)row * N + col;
            if (EPI == 0) {
                C[idx] = z;
            } else if (EPI == 1) {
                C[idx] = z > 0.0f ? z : 0.0f;
            } else if (EPI == 2) {
                float g = 1.0f / (1.0f + expf(-z));
                C[idx]  *= g;
                C2[idx] *= g;
            } else {  // EPI == 3
                C[idx] += z;
            }
        }
    }
}

// ---------------------------------------------------------------------------
// Depthwise conv1d (k=3, pad 1) over seq: out[b,l,d] = b[d] + sum_j x[b,l-1+j,d]*w[d,j]
// ---------------------------------------------------------------------------
__global__ void conv_kernel(const float* __restrict__ x,
                            const float* __restrict__ w,
                            const float* __restrict__ cb,
                            float* __restrict__ out) {
    size_t idx = (size_t)blockIdx.x * blockDim.x + threadIdx.x;
    if (idx >= (size_t)MM * DD) return;
    int d = (int)(idx % DD);
    int l = (int)((idx / DD) % LL);
    size_t base = idx;  // (b*LL + l)*DD + d
    float w0 = w[d * 3 + 0], w1 = w[d * 3 + 1], w2 = w[d * 3 + 2];
    float acc = cb[d] + w1 * x[base];
    if (l > 0)      acc += w0 * x[base - DD];
    if (l < LL - 1) acc += w2 * x[base + DD];
    out[base] = acc;
}

// ---------------------------------------------------------------------------
// Chunked cumsum over L (per b,r column), fused multiply with v_gated.
// ---------------------------------------------------------------------------
__global__ void scanA_kernel(const float* __restrict__ u, float* __restrict__ part) {
    int tid = blockIdx.x * blockDim.x + threadIdx.x;
    if (tid >= BB * NCHUNK * RR) return;
    int r = tid % RR;
    int c = (tid / RR) % NCHUNK;
    int b = tid / (RR * NCHUNK);
    size_t base = ((size_t)b * LL + c * CHLEN) * RR + r;
    float s = 0.0f;
    for (int l = 0; l < CHLEN; l++) s += u[base + (size_t)l * RR];
    part[((size_t)b * NCHUNK + c) * RR + r] = s;
}

__global__ void scanB_kernel(float* __restrict__ part) {
    int tid = blockIdx.x * blockDim.x + threadIdx.x;
    if (tid >= BB * RR) return;
    int r = tid % RR;
    int b = tid / RR;
    float run = 0.0f;
    for (int c = 0; c < NCHUNK; c++) {
        size_t idx = ((size_t)b * NCHUNK + c) * RR + r;
        float t = part[idx];
        part[idx] = run;   // exclusive prefix
        run += t;
    }
}

__global__ void scanC_kernel(const float* __restrict__ u, float* __restrict__ v,
                             const float* __restrict__ part) {
    int tid = blockIdx.x * blockDim.x + threadIdx.x;
    if (tid >= BB * NCHUNK * RR) return;
    int r = tid % RR;
    int c = (tid / RR) % NCHUNK;
    int b = tid / (RR * NCHUNK);
    float acc = part[((size_t)b * NCHUNK + c) * RR + r];
    size_t base = ((size_t)b * LL + c * CHLEN) * RR + r;
    for (int l = 0; l < CHLEN; l++) {
        size_t idx = base + (size_t)l * RR;
        acc += u[idx];
        v[idx] = acc * v[idx];   // global_out = cumsum(u_gated) * v_gated
    }
}

// ---------------------------------------------------------------------------
extern "C" void kernel_launch(void* const* d_in, const int* in_sizes, int n_in,
                              void* d_out, int out_size) {
    const float* x      = (const float*)d_in[0];
    const float* Wu     = (const float*)d_in[1];
    const float* bu     = (const float*)d_in[2];
    const float* Wv     = (const float*)d_in[3];
    const float* bv     = (const float*)d_in[4];
    const float* Wg1    = (const float*)d_in[5];
    const float* bg1    = (const float*)d_in[6];
    const float* Wg2    = (const float*)d_in[7];
    const float* bg2    = (const float*)d_in[8];
    const float* conv_w = (const float*)d_in[9];
    const float* conv_b = (const float*)d_in[10];
    float* out = (float*)d_out;

    float *pu, *pv, *ph, *ppart;
    cudaGetSymbolAddress((void**)&pu, g_u);
    cudaGetSymbolAddress((void**)&pv, g_v);
    cudaGetSymbolAddress((void**)&ph, g_h);
    cudaGetSymbolAddress((void**)&ppart, g_part);

    // 1. conv -> out (t term)
    {
        size_t n = (size_t)MM * DD;
        conv_kernel<<<(unsigned)((n + 255) / 256), 256>>>(x, conv_w, conv_b, out);
    }
    // 2. h = relu(x Wg1^T + bg1)
    sgemm_kernel<1><<<dim3(DH / BN, MM / BM), 256>>>(x, Wg1, bg1, ph, nullptr, MM, DH, DD);
    // 3. u = x Wu^T + bu
    sgemm_kernel<0><<<dim3(RR / BN, MM / BM), 256>>>(x, Wu, bu, pu, nullptr, MM, RR, DD);
    // 4. v = x Wv^T + bv
    sgemm_kernel<0><<<dim3(RR / BN, MM / BM), 256>>>(x, Wv, bv, pv, nullptr, MM, RR, DD);
    // 5. gates = sigmoid(h Wg2^T + bg2); u *= gates; v *= gates
    sgemm_kernel<2><<<dim3(RR / BN, MM / BM), 256>>>(ph, Wg2, bg2, pu, pv, MM, RR, DH);
    // 6. cumsum over L of u_gated, fused: v <- cumsum(u_gated) * v_gated
    scanA_kernel<<<(BB * NCHUNK * RR + 255) / 256, 256>>>(pu, ppart);
    scanB_kernel<<<(BB * RR + 255) / 256, 256>>>(ppart);
    scanC_kernel<<<(BB * NCHUNK * RR + 255) / 256, 256>>>(pu, pv, ppart);
    // 7. out += global_out @ Wu (n=d, k=r)
    sgemm_kernel<3><<<dim3(DD / BN, MM / BM), 256>>>(pv, Wu, nullptr, out, nullptr, MM, DD, RR);
}

// round 4
// speedup vs baseline: 2.6572x; 2.6572x over previous
#include <cuda_runtime.h>
#include <cuda_bf16.h>
#include <cstdint>
#include <math.h>

// ---------------- problem constants ----------------
#define BB 4
#define LL 2048
#define DD 2048
#define RR 2048
#define DHH 512
#define MM (BB * LL)          // 8192
#define NCH 16
#define CHL (LL / NCH)        // 128

// ---------------- GEMM tiling ----------------
// CTA tile 256x128, 8 warps (4x2), warp tile 64x64, BK=32 bf16 (64B rows)
#define TBM 256
#define TBN 128
#define TBK 32
#define A_TILE 16384          // 256*64B
#define B_TILE 8192           // 128*64B
#define STAGE_BYTES (2 * A_TILE + 2 * B_TILE)   // Ahi, Alo, Bhi, Blo = 49152
#define NSTAGE 3
#define SMEM_TOTAL (NSTAGE * STAGE_BYTES)       // 147456

// ---------------- device scratch ----------------
__device__ __nv_bfloat16 g_xhi[(size_t)MM * DD], g_xlo[(size_t)MM * DD];
__device__ __nv_bfloat16 g_wuhi[(size_t)RR * DD], g_wulo[(size_t)RR * DD];
__device__ __nv_bfloat16 g_wvhi[(size_t)RR * DD], g_wvlo[(size_t)RR * DD];
__device__ __nv_bfloat16 g_wg1hi[(size_t)DHH * DD], g_wg1lo[(size_t)DHH * DD];
__device__ __nv_bfloat16 g_wg2hi[(size_t)RR * DHH], g_wg2lo[(size_t)RR * DHH];
__device__ __nv_bfloat16 g_hhi[(size_t)MM * DHH], g_hlo[(size_t)MM * DHH];
__device__ __nv_bfloat16 g_ghi[(size_t)MM * RR], g_glo[(size_t)MM * RR];
__device__ float g_u[(size_t)MM * RR];
__device__ float g_v[(size_t)MM * RR];
__device__ float g_part[(size_t)BB * NCH * RR];

// ---------------- PTX helpers (arch-agnostic only) ----------------
__device__ __forceinline__ uint32_t smem_u32(const void* p) {
    uint32_t a;
    asm("{ .reg .u64 t; cvta.to.shared.u64 t, %1; cvt.u32.u64 %0, t; }" : "=r"(a) : "l"(p));
    return a;
}
__device__ __forceinline__ void cp16(uint32_t dst, const void* src) {
    asm volatile("cp.async.cg.shared.global [%0], [%1], 16;" :: "r"(dst), "l"(src));
}
#define CP_COMMIT() asm volatile("cp.async.commit_group;" ::: "memory")
#define CP_WAIT(n)  asm volatile("cp.async.wait_group %0;" :: "n"(n) : "memory")

#define LDSM4(r, addr) \
    asm volatile("ldmatrix.sync.aligned.m8n8.x4.shared.b16 {%0,%1,%2,%3}, [%4];" \
        : "=r"((r)[0]), "=r"((r)[1]), "=r"((r)[2]), "=r"((r)[3]) : "r"(addr))

__device__ __forceinline__ void mma16816(float* c, const uint32_t* a, uint32_t b0, uint32_t b1) {
    asm volatile(
        "mma.sync.aligned.m16n8k16.row.col.f32.bf16.bf16.f32 "
        "{%0,%1,%2,%3}, {%4,%5,%6,%7}, {%8,%9}, {%0,%1,%2,%3};"
        : "+f"(c[0]), "+f"(c[1]), "+f"(c[2]), "+f"(c[3])
        : "r"(a[0]), "r"(a[1]), "r"(a[2]), "r"(a[3]), "r"(b0), "r"(b1));
}

// swizzled smem offset for (row, 16B-chunk c) in a 64B-row tile
__device__ __forceinline__ uint32_t swz(int r, int c) {
    return (uint32_t)(r * 64 + ((c ^ ((r >> 1) & 3)) << 4));
}

// load one chunk's 4 tiles into a stage
__device__ __forceinline__ void load_ab(uint32_t st,
                                        const __nv_bfloat16* __restrict__ Ahi,
                                        const __nv_bfloat16* __restrict__ Alo,
                                        const __nv_bfloat16* __restrict__ Bhi,
                                        const __nv_bfloat16* __restrict__ Blo,
                                        int K, int row0, int col0, int k0, int tid) {
#pragma unroll
    for (int i = 0; i < 4; i++) {                 // A: 256 rows x 4 chunks
        int id = tid + i * 256;
        int r = id >> 2, c = id & 3;
        uint32_t dst = st + swz(r, c);
        size_t srcoff = (size_t)(row0 + r) * K + k0 + c * 8;
        cp16(dst,          Ahi + srcoff);
        cp16(dst + A_TILE, Alo + srcoff);
    }
#pragma unroll
    for (int i = 0; i < 2; i++) {                 // B: 128 rows x 4 chunks
        int id = tid + i * 256;
        int r = id >> 2, c = id & 3;
        uint32_t dst = st + 2 * A_TILE + swz(r, c);
        size_t srcoff = (size_t)(col0 + r) * K + k0 + c * 8;
        cp16(dst,          Bhi + srcoff);
        cp16(dst + B_TILE, Blo + srcoff);
    }
}

// ---------------------------------------------------------------------------
// bf16-split warp-MMA GEMM: C[m,n] = sum_k A[m,k]*B[n,k]
// EPI 0: C = z + bias
// EPI 1: relu(z + bias) -> bf16 split (Ohi, Olo)
// EPI 2: g = sigmoid(z + bias); C *= g; C2 *= g
// EPI 3: C += z
// ---------------------------------------------------------------------------
template <int EPI>
__global__ __launch_bounds__(256)
void bsgemm(const __nv_bfloat16* __restrict__ Ahi, const __nv_bfloat16* __restrict__ Alo,
            const __nv_bfloat16* __restrict__ Bhi, const __nv_bfloat16* __restrict__ Blo,
            const float* __restrict__ bias,
            float* __restrict__ C, float* __restrict__ C2,
            __nv_bfloat16* __restrict__ Ohi, __nv_bfloat16* __restrict__ Olo,
            int M, int N, int K) {
    extern __shared__ __align__(128) char smem[];
    const uint32_t sb = smem_u32(smem);
    const int tid  = threadIdx.x;
    const int wid  = tid >> 5;
    const int lane = tid & 31;
    const int wm = wid >> 1;          // 0..3 (m)
    const int wn = wid & 1;           // 0..1 (n)
    const int row0 = blockIdx.y * TBM;
    const int col0 = blockIdx.x * TBN;
    const int nchunks = K / TBK;

    // ldmatrix lane mapping
    const int lr = lane & 7;
    const int j  = lane >> 3;
    const int arow  = ((j & 1) << 3) + lr;   // A: row within 16-row frag
    const int acsel = j >> 1;                // A: chunk select (0/1)
    const int brow  = ((j >> 1) << 3) + lr;  // B: row within 16-row pair
    const int bcsel = j & 1;

    float acc[4][8][4];
#pragma unroll
    for (int mi = 0; mi < 4; mi++)
#pragma unroll
        for (int nj = 0; nj < 8; nj++)
#pragma unroll
            for (int q = 0; q < 4; q++) acc[mi][nj][q] = 0.0f;

    // prologue: chunks 0,1
#pragma unroll
    for (int p = 0; p < 2; p++) {
        load_ab(sb + p * STAGE_BYTES, Ahi, Alo, Bhi, Blo, K, row0, col0, p * TBK, tid);
        CP_COMMIT();
    }

    for (int c = 0; c < nchunks; c++) {
        if (c + 1 < nchunks) CP_WAIT(1); else CP_WAIT(0);
        __syncthreads();

        const int nxt = c + 2;
        if (nxt < nchunks) {
            load_ab(sb + (nxt % NSTAGE) * STAGE_BYTES, Ahi, Alo, Bhi, Blo,
                    K, row0, col0, nxt * TBK, tid);
            CP_COMMIT();
        }

        const uint32_t sA = sb + (c % NSTAGE) * STAGE_BYTES;
        const uint32_t sB = sA + 2 * A_TILE;

#pragma unroll
        for (int s = 0; s < 2; s++) {
            uint32_t ah[4][4], bh[4][4], fx[4][4];
            uint32_t adA[4], adB[4];
#pragma unroll
            for (int mi = 0; mi < 4; mi++) {
                int r = wm * 64 + mi * 16 + arow;
                adA[mi] = sA + swz(r, 2 * s + acsel);
                LDSM4(ah[mi], adA[mi]);
            }
#pragma unroll
            for (int p = 0; p < 4; p++) {
                int r = wn * 64 + p * 16 + brow;
                adB[p] = sB + swz(r, 2 * s + bcsel);
                LDSM4(bh[p], adB[p]);
            }
            // pass 1: Ahi x Bhi
#pragma unroll
            for (int mi = 0; mi < 4; mi++)
#pragma unroll
                for (int nj = 0; nj < 8; nj++)
                    mma16816(acc[mi][nj], ah[mi], bh[nj >> 1][(nj & 1) * 2], bh[nj >> 1][(nj & 1) * 2 + 1]);
            // pass 2: Alo x Bhi
#pragma unroll
            for (int mi = 0; mi < 4; mi++) LDSM4(fx[mi], adA[mi] + A_TILE);
#pragma unroll
            for (int mi = 0; mi < 4; mi++)
#pragma unroll
                for (int nj = 0; nj < 8; nj++)
                    mma16816(acc[mi][nj], fx[mi], bh[nj >> 1][(nj & 1) * 2], bh[nj >> 1][(nj & 1) * 2 + 1]);
            // pass 3: Ahi x Blo
#pragma unroll
            for (int p = 0; p < 4; p++) LDSM4(fx[p], adB[p] + B_TILE);
#pragma unroll
            for (int mi = 0; mi < 4; mi++)
#pragma unroll
                for (int nj = 0; nj < 8; nj++)
                    mma16816(acc[mi][nj], ah[mi], fx[nj >> 1][(nj & 1) * 2], fx[nj >> 1][(nj & 1) * 2 + 1]);
        }
    }

    // -------- epilogue --------
    const int g = lane >> 2, t = lane & 3;
#pragma unroll
    for (int mi = 0; mi < 4; mi++) {
#pragma unroll
        for (int nj = 0; nj < 8; nj++) {
            int row = row0 + wm * 64 + mi * 16 + g;
            int col = col0 + wn * 64 + nj * 8 + 2 * t;
            size_t i0 = (size_t)row * N + col;
            size_t i1 = (size_t)(row + 8) * N + col;
            float* z = acc[mi][nj];
            if (EPI == 0) {
                float b0 = bias[col], b1 = bias[col + 1];
                *(float2*)(C + i0) = make_float2(z[0] + b0, z[1] + b1);
                *(float2*)(C + i1) = make_float2(z[2] + b0, z[3] + b1);
            } else if (EPI == 1) {
                float b0 = bias[col], b1 = bias[col + 1];
                float v0 = fmaxf(z[0] + b0, 0.0f), v1 = fmaxf(z[1] + b1, 0.0f);
                float v2 = fmaxf(z[2] + b0, 0.0f), v3 = fmaxf(z[3] + b1, 0.0f);
                __nv_bfloat16 h0 = __float2bfloat16(v0), h1 = __float2bfloat16(v1);
                __nv_bfloat16 h2 = __float2bfloat16(v2), h3 = __float2bfloat16(v3);
                *(__nv_bfloat162*)(Ohi + i0) = __halves2bfloat162(h0, h1);
                *(__nv_bfloat162*)(Ohi + i1) = __halves2bfloat162(h2, h3);
                *(__nv_bfloat162*)(Olo + i0) = __halves2bfloat162(
                    __float2bfloat16(v0 - __bfloat162float(h0)), __float2bfloat16(v1 - __bfloat162float(h1)));
                *(__nv_bfloat162*)(Olo + i1) = __halves2bfloat162(
                    __float2bfloat16(v2 - __bfloat162float(h2)), __float2bfloat16(v3 - __bfloat162float(h3)));
            } else if (EPI == 2) {
                float b0 = bias[col], b1 = bias[col + 1];
                float g0 = 1.0f / (1.0f + __expf(-(z[0] + b0)));
                float g1 = 1.0f / (1.0f + __expf(-(z[1] + b1)));
                float g2 = 1.0f / (1.0f + __expf(-(z[2] + b0)));
                float g3 = 1.0f / (1.0f + __expf(-(z[3] + b1)));
                float2 u0 = *(float2*)(C + i0), u1 = *(float2*)(C + i1);
                float2 v0 = *(float2*)(C2 + i0), v1 = *(float2*)(C2 + i1);
                u0.x *= g0; u0.y *= g1; u1.x *= g2; u1.y *= g3;
                v0.x *= g0; v0.y *= g1; v1.x *= g2; v1.y *= g3;
                *(float2*)(C + i0) = u0; *(float2*)(C + i1) = u1;
                *(float2*)(C2 + i0) = v0; *(float2*)(C2 + i1) = v1;
            } else {  // EPI == 3
                float2 o0 = *(float2*)(C + i0), o1 = *(float2*)(C + i1);
                o0.x += z[0]; o0.y += z[1]; o1.x += z[2]; o1.y += z[3];
                *(float2*)(C + i0) = o0; *(float2*)(C + i1) = o1;
            }
        }
    }
}

// ---------------------------------------------------------------------------
// elementwise kernels
// ---------------------------------------------------------------------------
__global__ void split_kernel(const float* __restrict__ s, __nv_bfloat16* __restrict__ hi,
                             __nv_bfloat16* __restrict__ lo, size_t n) {
    size_t i = ((size_t)blockIdx.x * blockDim.x + threadIdx.x) * 4;
    if (i >= n) return;
    float4 v = *(const float4*)(s + i);
    __nv_bfloat16 h0 = __float2bfloat16(v.x), h1 = __float2bfloat16(v.y);
    __nv_bfloat16 h2 = __float2bfloat16(v.z), h3 = __float2bfloat16(v.w);
    *(__nv_bfloat162*)(hi + i)     = __halves2bfloat162(h0, h1);
    *(__nv_bfloat162*)(hi + i + 2) = __halves2bfloat162(h2, h3);
    *(__nv_bfloat162*)(lo + i)     = __halves2bfloat162(
        __float2bfloat16(v.x - __bfloat162float(h0)), __float2bfloat16(v.y - __bfloat162float(h1)));
    *(__nv_bfloat162*)(lo + i + 2) = __halves2bfloat162(
        __float2bfloat16(v.z - __bfloat162float(h2)), __float2bfloat16(v.w - __bfloat162float(h3)));
}

__global__ void conv_kernel(const float* __restrict__ x, const float* __restrict__ w,
                            const float* __restrict__ cb, float* __restrict__ out) {
    size_t idx = (size_t)blockIdx.x * blockDim.x + threadIdx.x;
    if (idx >= (size_t)MM * DD) return;
    int d = (int)(idx % DD);
    int l = (int)((idx / DD) % LL);
    float w0 = w[d * 3 + 0], w1 = w[d * 3 + 1], w2 = w[d * 3 + 2];
    float acc = cb[d] + w1 * x[idx];
    if (l > 0)      acc += w0 * x[idx - DD];
    if (l < LL - 1) acc += w2 * x[idx + DD];
    out[idx] = acc;
}

__global__ void scanA_kernel(const float* __restrict__ u, float* __restrict__ part) {
    int tid = blockIdx.x * blockDim.x + threadIdx.x;
    if (tid >= BB * NCH * RR) return;
    int r = tid % RR;
    int c = (tid / RR) % NCH;
    int b = tid / (RR * NCH);
    size_t base = ((size_t)b * LL + c * CHL) * RR + r;
    float s = 0.0f;
    for (int l = 0; l < CHL; l++) s += u[base + (size_t)l * RR];
    part[((size_t)b * NCH + c) * RR + r] = s;
}

__global__ void scanB_kernel(float* __restrict__ part) {
    int tid = blockIdx.x * blockDim.x + threadIdx.x;
    if (tid >= BB * RR) return;
    int r = tid % RR;
    int b = tid / RR;
    float run = 0.0f;
    for (int c = 0; c < NCH; c++) {
        size_t idx = ((size_t)b * NCH + c) * RR + r;
        float t = part[idx];
        part[idx] = run;
        run += t;
    }
}

__global__ void scanC_kernel(const float* __restrict__ u, const float* __restrict__ v,
                             const float* __restrict__ part,
                             __nv_bfloat16* __restrict__ ghi, __nv_bfloat16* __restrict__ glo) {
    int tid = blockIdx.x * blockDim.x + threadIdx.x;
    if (tid >= BB * NCH * RR) return;
    int r = tid % RR;
    int c = (tid / RR) % NCH;
    int b = tid / (RR * NCH);
    float acc = part[((size_t)b * NCH + c) * RR + r];
    size_t base = ((size_t)b * LL + c * CHL) * RR + r;
    for (int l = 0; l < CHL; l++) {
        size_t idx = base + (size_t)l * RR;
        acc += u[idx];
        float go = acc * v[idx];
        __nv_bfloat16 h = __float2bfloat16(go);
        ghi[idx] = h;
        glo[idx] = __float2bfloat16(go - __bfloat162float(h));
    }
}

// ---------------------------------------------------------------------------
extern "C" void kernel_launch(void* const* d_in, const int* in_sizes, int n_in,
                              void* d_out, int out_size) {
    const float* x      = (const float*)d_in[0];
    const float* Wu     = (const float*)d_in[1];
    const float* bu     = (const float*)d_in[2];
    const float* Wv     = (const float*)d_in[3];
    const float* bv     = (const float*)d_in[4];
    const float* Wg1    = (const float*)d_in[5];
    const float* bg1    = (const float*)d_in[6];
    const float* Wg2    = (const float*)d_in[7];
    const float* bg2    = (const float*)d_in[8];
    const float* conv_w = (const float*)d_in[9];
    const float* conv_b = (const float*)d_in[10];
    float* out = (float*)d_out;

    __nv_bfloat16 *xhi, *xlo, *wuhi, *wulo, *wvhi, *wvlo, *wg1hi, *wg1lo,
                  *wg2hi, *wg2lo, *hhi, *hlo, *ghi, *glo;
    float *pu, *pv, *ppart;
    cudaGetSymbolAddress((void**)&xhi, g_xhi);     cudaGetSymbolAddress((void**)&xlo, g_xlo);
    cudaGetSymbolAddress((void**)&wuhi, g_wuhi);   cudaGetSymbolAddress((void**)&wulo, g_wulo);
    cudaGetSymbolAddress((void**)&wvhi, g_wvhi);   cudaGetSymbolAddress((void**)&wvlo, g_wvlo);
    cudaGetSymbolAddress((void**)&wg1hi, g_wg1hi); cudaGetSymbolAddress((void**)&wg1lo, g_wg1lo);
    cudaGetSymbolAddress((void**)&wg2hi, g_wg2hi); cudaGetSymbolAddress((void**)&wg2lo, g_wg2lo);
    cudaGetSymbolAddress((void**)&hhi, g_hhi);     cudaGetSymbolAddress((void**)&hlo, g_hlo);
    cudaGetSymbolAddress((void**)&ghi, g_ghi);     cudaGetSymbolAddress((void**)&glo, g_glo);
    cudaGetSymbolAddress((void**)&pu, g_u);        cudaGetSymbolAddress((void**)&pv, g_v);
    cudaGetSymbolAddress((void**)&ppart, g_part);

    cudaFuncSetAttribute(bsgemm<0>, cudaFuncAttributeMaxDynamicSharedMemorySize, SMEM_TOTAL);
    cudaFuncSetAttribute(bsgemm<1>, cudaFuncAttributeMaxDynamicSharedMemorySize, SMEM_TOTAL);
    cudaFuncSetAttribute(bsgemm<2>, cudaFuncAttributeMaxDynamicSharedMemorySize, SMEM_TOTAL);
    cudaFuncSetAttribute(bsgemm<3>, cudaFuncAttributeMaxDynamicSharedMemorySize, SMEM_TOTAL);

    // conversions
    split_kernel<<<(unsigned)((size_t)MM * DD / 4 / 256), 256>>>(x, xhi, xlo, (size_t)MM * DD);
    split_kernel<<<(unsigned)((size_t)RR * DD / 4 / 256), 256>>>(Wu, wuhi, wulo, (size_t)RR * DD);
    split_kernel<<<(unsigned)((size_t)RR * DD / 4 / 256), 256>>>(Wv, wvhi, wvlo, (size_t)RR * DD);
    split_kernel<<<(unsigned)((size_t)DHH * DD / 4 / 256), 256>>>(Wg1, wg1hi, wg1lo, (size_t)DHH * DD);
    split_kernel<<<(unsigned)((size_t)RR * DHH / 4 / 256), 256>>>(Wg2, wg2hi, wg2lo, (size_t)RR * DHH);

    // conv -> out (T term)
    conv_kernel<<<(unsigned)(((size_t)MM * DD + 255) / 256), 256>>>(x, conv_w, conv_b, out);

    // h = relu(x Wg1^T + bg1) -> bf16 split
    bsgemm<1><<<dim3(DHH / TBN, MM / TBM), 256, SMEM_TOTAL>>>(
        xhi, xlo, wg1hi, wg1lo, bg1, nullptr, nullptr, hhi, hlo, MM, DHH, DD);
    // u = x Wu^T + bu
    bsgemm<0><<<dim3(RR / TBN, MM / TBM), 256, SMEM_TOTAL>>>(
        xhi, xlo, wuhi, wulo, bu, pu, nullptr, nullptr, nullptr, MM, RR, DD);
    // v = x Wv^T + bv
    bsgemm<0><<<dim3(RR / TBN, MM / TBM), 256, SMEM_TOTAL>>>(
        xhi, xlo, wvhi, wvlo, bv, pv, nullptr, nullptr, nullptr, MM, RR, DD);
    // gates = sigmoid(h Wg2^T + bg2); u *= g; v *= g
    bsgemm<2><<<dim3(RR / TBN, MM / TBM), 256, SMEM_TOTAL>>>(
        hhi, hlo, wg2hi, wg2lo, bg2, pu, pv, nullptr, nullptr, MM, RR, DHH);

    // cumsum over L; global_out = cumsum(u_gated) * v_gated -> bf16 split
    scanA_kernel<<<(BB * NCH * RR + 255) / 256, 256>>>(pu, ppart);
    scanB_kernel<<<(BB * RR + 255) / 256, 256>>>(ppart);
    scanC_kernel<<<(BB * NCH * RR + 255) / 256, 256>>>(pu, pv, ppart, ghi, glo);

    // out += global_out @ B where B[n=d][k=r] = Wu[d][r] -> the Wu buffer itself
    // (reference: einsum("blr,rd->bld", go, Wu.T[:R,:]) and Wu.T[r,d] = Wu[d,r])
    bsgemm<3><<<dim3(DD / TBN, MM / TBM), 256, SMEM_TOTAL>>>(
        ghi, glo, wuhi, wulo, nullptr, out, nullptr, nullptr, nullptr, MM, DD, RR);
}